// round 1
// baseline (speedup 1.0000x reference)
#include <cuda_runtime.h>

#define NSLICE 24
#define H 256
#define W 256
#define OH 512
#define OW 512

// One block = one output row-pair (rows 2r, 2r+1) of one (b,s) image.
// 128 threads; thread t produces output cols [4t, 4t+3] of both rows
// as two float4 stores. Input rows r-1, r, r+1 staged in smem with halo.
__global__ __launch_bounds__(128, 12) void convT_kernel(
    const float* __restrict__ x,
    const float* __restrict__ w,
    const float* __restrict__ bias,
    float* __restrict__ out)
{
    __shared__ float sw[17];           // 16 weights + bias
    __shared__ float row[3][W + 2];    // cols -1..256 -> idx 0..257 (zero halo)

    const int t  = threadIdx.x;        // 0..127
    const int r  = blockIdx.x;         // 0..255 -> output rows 2r, 2r+1
    const int bs = blockIdx.y;         // 0..B*NSLICE-1
    const int s  = bs % NSLICE;

    if (t < 16)       sw[t]  = w[s * 16 + t];
    else if (t == 16) sw[16] = bias[s];

    const float* xb = x + (size_t)bs * (H * W);
    #pragma unroll
    for (int j = 0; j < 3; ++j) {
        const int iy = r - 1 + j;
        float2 v = make_float2(0.f, 0.f);
        if (iy >= 0 && iy < H)
            v = *reinterpret_cast<const float2*>(xb + iy * W + 2 * t);
        row[j][2 * t + 1] = v.x;
        row[j][2 * t + 2] = v.y;
        if (t == 0) { row[j][0] = 0.f; row[j][W + 1] = 0.f; }
    }
    __syncthreads();

    // smem idx = ix + 1; thread needs ix in {2t-1, 2t, 2t+1, 2t+2} -> idx 2t..2t+3
    float m1[4], r0[4], p1[4];
    #pragma unroll
    for (int i = 0; i < 4; ++i) {
        m1[i] = row[0][2 * t + i];
        r0[i] = row[1][2 * t + i];
        p1[i] = row[2][2 * t + i];
    }

    const float w00 = sw[0],  w01 = sw[1],  w02 = sw[2],  w03 = sw[3];
    const float w10 = sw[4],  w11 = sw[5],  w12 = sw[6],  w13 = sw[7];
    const float w20 = sw[8],  w21 = sw[9],  w22 = sw[10], w23 = sw[11];
    const float w30 = sw[12], w31 = sw[13], w32 = sw[14], w33 = sw[15];
    const float b0  = sw[16];

    // Row 2r   (even oy): iy=r-1 (ky=3), iy=r (ky=1)
    // Row 2r+1 (odd  oy): iy=r   (ky=2), iy=r+1 (ky=0)
    // Col 4t   (even ox=2c', c'=2t  ): ix=c'-1 (kx=3), ix=c' (kx=1) -> v[0],v[1]
    // Col 4t+1 (odd  ox,    c'=2t  ): ix=c'   (kx=2), ix=c'+1(kx=0) -> v[1],v[2]
    // Col 4t+2 (even ox,    c'=2t+1): ix=c'-1 (kx=3), ix=c' (kx=1) -> v[1],v[2]
    // Col 4t+3 (odd  ox,    c'=2t+1): ix=c'   (kx=2), ix=c'+1(kx=0) -> v[2],v[3]
    float4 top, bot;
    top.x = w33 * m1[0] + w31 * m1[1] + w13 * r0[0] + w11 * r0[1] + b0;
    top.y = w32 * m1[1] + w30 * m1[2] + w12 * r0[1] + w10 * r0[2] + b0;
    top.z = w33 * m1[1] + w31 * m1[2] + w13 * r0[1] + w11 * r0[2] + b0;
    top.w = w32 * m1[2] + w30 * m1[3] + w12 * r0[2] + w10 * r0[3] + b0;

    bot.x = w23 * r0[0] + w21 * r0[1] + w03 * p1[0] + w01 * p1[1] + b0;
    bot.y = w22 * r0[1] + w20 * r0[2] + w02 * p1[1] + w00 * p1[2] + b0;
    bot.z = w23 * r0[1] + w21 * r0[2] + w03 * p1[1] + w01 * p1[2] + b0;
    bot.w = w22 * r0[2] + w20 * r0[3] + w02 * p1[2] + w00 * p1[3] + b0;

    float* ob = out + (size_t)bs * (OH * OW);
    *reinterpret_cast<float4*>(ob + (size_t)(2 * r)     * OW + 4 * t) = top;
    *reinterpret_cast<float4*>(ob + (size_t)(2 * r + 1) * OW + 4 * t) = bot;
}

extern "C" void kernel_launch(void* const* d_in, const int* in_sizes, int n_in,
                              void* d_out, int out_size) {
    const float* x = (const float*)d_in[0];
    const float* w = (const float*)d_in[1];
    const float* b = (const float*)d_in[2];
    float* out = (float*)d_out;

    const int B = in_sizes[0] / (NSLICE * H * W);   // = 8
    dim3 grid(H, B * NSLICE);                        // 256 row-pairs x 192 images
    convT_kernel<<<grid, 128>>>(x, w, b, out);
}

// round 2
// speedup vs baseline: 1.3362x; 1.3362x over previous
#include <cuda_runtime.h>

#define NSLICE 24
#define H 256
#define W 256
#define OH 512
#define OW 512

// One block = one output row-pair (rows 2r, 2r+1) of one (b,s) image.
// 128 threads; thread t produces output cols [4t, 4t+3] of both rows.
// No shared memory: halos come from warp shuffles; warp-edge lanes do a
// scalar LDG fallback (L2 hit). Weights loaded as uniform float4 broadcasts.
__global__ __launch_bounds__(128, 16) void convT_kernel(
    const float* __restrict__ x,
    const float* __restrict__ w,
    const float* __restrict__ bias,
    float* __restrict__ out)
{
    const int t  = threadIdx.x;        // 0..127
    const int r  = blockIdx.x;         // 0..255 -> output rows 2r, 2r+1
    const int bs = blockIdx.y;         // 0..B*NSLICE-1
    const int s  = bs % NSLICE;

    // Uniform (warp-broadcast) weight loads: 4x LDG.128 + 1 scalar.
    const float4 wr0 = *reinterpret_cast<const float4*>(w + s * 16 + 0);
    const float4 wr1 = *reinterpret_cast<const float4*>(w + s * 16 + 4);
    const float4 wr2 = *reinterpret_cast<const float4*>(w + s * 16 + 8);
    const float4 wr3 = *reinterpret_cast<const float4*>(w + s * 16 + 12);
    const float b0 = bias[s];

    const float* xb = x + (size_t)bs * (H * W);

    // Per row j (iy = r-1+j): center pair (cx=x[2t], cy=x[2t+1]),
    // left halo L (x[2t-1]), right halo R (x[2t+2]).
    float cx[3], cy[3], L[3], R[3];
    #pragma unroll
    for (int j = 0; j < 3; ++j) {
        const int iy = r - 1 + j;
        float2 v = make_float2(0.f, 0.f);
        if (iy >= 0 && iy < H)
            v = *reinterpret_cast<const float2*>(xb + iy * W + 2 * t);
        cx[j] = v.x;
        cy[j] = v.y;
    }

    const unsigned full = 0xFFFFFFFFu;
    #pragma unroll
    for (int j = 0; j < 3; ++j) {
        L[j] = __shfl_up_sync(full, cy[j], 1);
        R[j] = __shfl_down_sync(full, cx[j], 1);
    }

    const int lane = t & 31;
    if (lane == 0) {
        #pragma unroll
        for (int j = 0; j < 3; ++j) {
            const int iy = r - 1 + j;
            L[j] = (t > 0 && iy >= 0 && iy < H) ? xb[iy * W + 2 * t - 1] : 0.f;
        }
    }
    if (lane == 31) {
        #pragma unroll
        for (int j = 0; j < 3; ++j) {
            const int iy = r - 1 + j;
            R[j] = (2 * t + 2 < W && iy >= 0 && iy < H) ? xb[iy * W + 2 * t + 2] : 0.f;
        }
    }

    const float w00 = wr0.x, w01 = wr0.y, w02 = wr0.z, w03 = wr0.w;
    const float w10 = wr1.x, w11 = wr1.y, w12 = wr1.z, w13 = wr1.w;
    const float w20 = wr2.x, w21 = wr2.y, w22 = wr2.z, w23 = wr2.w;
    const float w30 = wr3.x, w31 = wr3.y, w32 = wr3.z, w33 = wr3.w;

    // Row 2r   (even oy): rows (r-1: ky=3), (r: ky=1)   -> j=0, j=1
    // Row 2r+1 (odd  oy): rows (r: ky=2), (r+1: ky=0)   -> j=1, j=2
    // Cols: [L, cx, cy, R] correspond to ix = 2t-1, 2t, 2t+1, 2t+2.
    float4 top, bot;
    top.x = w33 * L[0]  + w31 * cx[0] + w13 * L[1]  + w11 * cx[1] + b0;
    top.y = w32 * cx[0] + w30 * cy[0] + w12 * cx[1] + w10 * cy[1] + b0;
    top.z = w33 * cx[0] + w31 * cy[0] + w13 * cx[1] + w11 * cy[1] + b0;
    top.w = w32 * cy[0] + w30 * R[0]  + w12 * cy[1] + w10 * R[1]  + b0;

    bot.x = w23 * L[1]  + w21 * cx[1] + w03 * L[2]  + w01 * cx[2] + b0;
    bot.y = w22 * cx[1] + w20 * cy[1] + w02 * cx[2] + w00 * cy[2] + b0;
    bot.z = w23 * cx[1] + w21 * cy[1] + w03 * cx[2] + w01 * cy[2] + b0;
    bot.w = w22 * cy[1] + w20 * R[1]  + w02 * cy[2] + w00 * R[2]  + b0;

    float* ob = out + (size_t)bs * (OH * OW);
    *reinterpret_cast<float4*>(ob + (size_t)(2 * r)     * OW + 4 * t) = top;
    *reinterpret_cast<float4*>(ob + (size_t)(2 * r + 1) * OW + 4 * t) = bot;
}

extern "C" void kernel_launch(void* const* d_in, const int* in_sizes, int n_in,
                              void* d_out, int out_size) {
    const float* x = (const float*)d_in[0];
    const float* w = (const float*)d_in[1];
    const float* b = (const float*)d_in[2];
    float* out = (float*)d_out;

    const int B = in_sizes[0] / (NSLICE * H * W);   // = 8
    dim3 grid(H, B * NSLICE);                        // 256 row-pairs x 192 images
    convT_kernel<<<grid, 128>>>(x, w, b, out);
}

// round 3
// speedup vs baseline: 1.4974x; 1.1206x over previous
#include <cuda_runtime.h>

#define NSLICE 24
#define H 256
#define W 256
#define OH 512
#define OW 512

// One block = 4 output rows (two row-pairs) of one (b,s) image: rows 4g..4g+3.
// 128 threads; thread t produces output cols [4t, 4t+3] of all 4 rows
// (four perfectly-coalesced float4 stores). Inputs: 4 rows (iy = 2g-1 .. 2g+2),
// each thread loads its float2 (ix = 2t, 2t+1); halos via warp shuffle with
// scalar-LDG fallback at warp edges. No shared memory.
__global__ __launch_bounds__(128, 8) void convT_kernel(
    const float* __restrict__ x,
    const float* __restrict__ w,
    const float* __restrict__ bias,
    float* __restrict__ out)
{
    const int t  = threadIdx.x;        // 0..127
    const int g  = blockIdx.x;         // 0..127 -> output rows 4g..4g+3
    const int bs = blockIdx.y;         // 0..B*NSLICE-1
    const int s  = bs % NSLICE;

    // Uniform (warp-broadcast) weight loads.
    const float4 wr0 = *reinterpret_cast<const float4*>(w + s * 16 + 0);
    const float4 wr1 = *reinterpret_cast<const float4*>(w + s * 16 + 4);
    const float4 wr2 = *reinterpret_cast<const float4*>(w + s * 16 + 8);
    const float4 wr3 = *reinterpret_cast<const float4*>(w + s * 16 + 12);
    const float b0 = bias[s];

    const float* xb = x + (size_t)bs * (H * W);

    // 4 input rows j=0..3: iy = 2g - 1 + j.
    float cx[4], cy[4], L[4], R[4];
    #pragma unroll
    for (int j = 0; j < 4; ++j) {
        const int iy = 2 * g - 1 + j;
        float2 v = make_float2(0.f, 0.f);
        if (iy >= 0 && iy < H)
            v = *reinterpret_cast<const float2*>(xb + iy * W + 2 * t);
        cx[j] = v.x;
        cy[j] = v.y;
    }

    const unsigned full = 0xFFFFFFFFu;
    #pragma unroll
    for (int j = 0; j < 4; ++j) {
        L[j] = __shfl_up_sync(full, cy[j], 1);
        R[j] = __shfl_down_sync(full, cx[j], 1);
    }

    const int lane = t & 31;
    if (lane == 0) {
        #pragma unroll
        for (int j = 0; j < 4; ++j) {
            const int iy = 2 * g - 1 + j;
            L[j] = (t > 0 && iy >= 0 && iy < H) ? xb[iy * W + 2 * t - 1] : 0.f;
        }
    }
    if (lane == 31) {
        #pragma unroll
        for (int j = 0; j < 4; ++j) {
            const int iy = 2 * g - 1 + j;
            R[j] = (2 * t + 2 < W && iy >= 0 && iy < H) ? xb[iy * W + 2 * t + 2] : 0.f;
        }
    }

    const float w00 = wr0.x, w01 = wr0.y, w02 = wr0.z, w03 = wr0.w;
    const float w10 = wr1.x, w11 = wr1.y, w12 = wr1.z, w13 = wr1.w;
    const float w20 = wr2.x, w21 = wr2.y, w22 = wr2.z, w23 = wr2.w;
    const float w30 = wr3.x, w31 = wr3.y, w32 = wr3.z, w33 = wr3.w;

    float* ob = out + (size_t)bs * (OH * OW) + 4 * t;
    const size_t orow = (size_t)4 * g * OW;

    // Output row uses two input rows ja (kernel row a) and jb (kernel row b):
    //  out row 4g   (even): ja=0 w3*, jb=1 w1*
    //  out row 4g+1 (odd ): ja=1 w2*, jb=2 w0*
    //  out row 4g+2 (even): ja=1 w3*, jb=2 w1*
    //  out row 4g+3 (odd ): ja=2 w2*, jb=3 w0*
    // Col pattern (ix = 2t-1..2t+2 -> L, cx, cy, R):
    //  .x = a3*L  + a1*cx + b3*L  + b1*cx
    //  .y = a2*cx + a0*cy + b2*cx + b0*cy
    //  .z = a3*cx + a1*cy + b3*cx + b1*cy
    //  .w = a2*cy + a0*R  + b2*cy + b0*R
#define OUT_ROW(dst, ja, a0_, a1_, a2_, a3_, jb, c0_, c1_, c2_, c3_)           \
    {                                                                          \
        float4 o;                                                              \
        o.x = a3_ * L[ja]  + a1_ * cx[ja] + c3_ * L[jb]  + c1_ * cx[jb] + b0;  \
        o.y = a2_ * cx[ja] + a0_ * cy[ja] + c2_ * cx[jb] + c0_ * cy[jb] + b0;  \
        o.z = a3_ * cx[ja] + a1_ * cy[ja] + c3_ * cx[jb] + c1_ * cy[jb] + b0;  \
        o.w = a2_ * cy[ja] + a0_ * R[ja]  + c2_ * cy[jb] + c0_ * R[jb]  + b0;  \
        *reinterpret_cast<float4*>(dst) = o;                                   \
    }

    OUT_ROW(ob + orow + 0 * OW, 0, w30, w31, w32, w33, 1, w10, w11, w12, w13);
    OUT_ROW(ob + orow + 1 * OW, 1, w20, w21, w22, w23, 2, w00, w01, w02, w03);
    OUT_ROW(ob + orow + 2 * OW, 1, w30, w31, w32, w33, 2, w10, w11, w12, w13);
    OUT_ROW(ob + orow + 3 * OW, 2, w20, w21, w22, w23, 3, w00, w01, w02, w03);
#undef OUT_ROW
}

extern "C" void kernel_launch(void* const* d_in, const int* in_sizes, int n_in,
                              void* d_out, int out_size) {
    const float* x = (const float*)d_in[0];
    const float* w = (const float*)d_in[1];
    const float* b = (const float*)d_in[2];
    float* out = (float*)d_out;

    const int B = in_sizes[0] / (NSLICE * H * W);   // = 8
    dim3 grid(OH / 4, B * NSLICE);                   // 128 x 192
    convT_kernel<<<grid, 128>>>(x, w, b, out);
}

// round 4
// speedup vs baseline: 1.5424x; 1.0301x over previous
#include <cuda_runtime.h>

#define NSLICE 24
#define H 256
#define W 256
#define OH 512
#define OW 512

// One block = 4 output rows (two row-pairs) of one (b,s) image: rows 4g..4g+3.
// 128 threads; thread t produces output cols [4t, 4t+3] of all 4 rows via
// streaming float4 stores (output is write-once -> evict-first, keep L2 for
// input). Inputs: 4 rows (iy = 2g-1..2g+2) as per-thread float2 loads; halos
// via warp shuffle with scalar-LDG fallback at warp edges. No shared memory.
__global__ __launch_bounds__(128, 12) void convT_kernel(
    const float* __restrict__ x,
    const float* __restrict__ w,
    const float* __restrict__ bias,
    float* __restrict__ out)
{
    const int t  = threadIdx.x;        // 0..127
    const int g  = blockIdx.x;         // 0..127 -> output rows 4g..4g+3
    const int bs = blockIdx.y;         // 0..B*NSLICE-1
    const int s  = bs % NSLICE;

    // Uniform (warp-broadcast) weight loads.
    const float4 wr0 = *reinterpret_cast<const float4*>(w + s * 16 + 0);
    const float4 wr1 = *reinterpret_cast<const float4*>(w + s * 16 + 4);
    const float4 wr2 = *reinterpret_cast<const float4*>(w + s * 16 + 8);
    const float4 wr3 = *reinterpret_cast<const float4*>(w + s * 16 + 12);
    const float b0 = bias[s];

    const float* xb = x + (size_t)bs * (H * W);

    // 4 input rows j=0..3: iy = 2g - 1 + j.
    float cx[4], cy[4], L[4], R[4];
    #pragma unroll
    for (int j = 0; j < 4; ++j) {
        const int iy = 2 * g - 1 + j;
        float2 v = make_float2(0.f, 0.f);
        if (iy >= 0 && iy < H)
            v = *reinterpret_cast<const float2*>(xb + iy * W + 2 * t);
        cx[j] = v.x;
        cy[j] = v.y;
    }

    const unsigned full = 0xFFFFFFFFu;
    #pragma unroll
    for (int j = 0; j < 4; ++j) {
        L[j] = __shfl_up_sync(full, cy[j], 1);
        R[j] = __shfl_down_sync(full, cx[j], 1);
    }

    const int lane = t & 31;
    if (lane == 0) {
        #pragma unroll
        for (int j = 0; j < 4; ++j) {
            const int iy = 2 * g - 1 + j;
            L[j] = (t > 0 && iy >= 0 && iy < H) ? xb[iy * W + 2 * t - 1] : 0.f;
        }
    }
    if (lane == 31) {
        #pragma unroll
        for (int j = 0; j < 4; ++j) {
            const int iy = 2 * g - 1 + j;
            R[j] = (2 * t + 2 < W && iy >= 0 && iy < H) ? xb[iy * W + 2 * t + 2] : 0.f;
        }
    }

    const float w00 = wr0.x, w01 = wr0.y, w02 = wr0.z, w03 = wr0.w;
    const float w10 = wr1.x, w11 = wr1.y, w12 = wr1.z, w13 = wr1.w;
    const float w20 = wr2.x, w21 = wr2.y, w22 = wr2.z, w23 = wr2.w;
    const float w30 = wr3.x, w31 = wr3.y, w32 = wr3.z, w33 = wr3.w;

    float* ob = out + (size_t)bs * (OH * OW) + 4 * t;
    const size_t orow = (size_t)4 * g * OW;

    // Output row uses two input rows ja (kernel row a*) and jb (kernel row c*):
    //  out 4g   (even): ja=0 w3*, jb=1 w1*
    //  out 4g+1 (odd ): ja=1 w2*, jb=2 w0*
    //  out 4g+2 (even): ja=1 w3*, jb=2 w1*
    //  out 4g+3 (odd ): ja=2 w2*, jb=3 w0*
#define OUT_ROW(dst, ja, a0_, a1_, a2_, a3_, jb, c0_, c1_, c2_, c3_)           \
    {                                                                          \
        float4 o;                                                              \
        o.x = a3_ * L[ja]  + a1_ * cx[ja] + c3_ * L[jb]  + c1_ * cx[jb] + b0;  \
        o.y = a2_ * cx[ja] + a0_ * cy[ja] + c2_ * cx[jb] + c0_ * cy[jb] + b0;  \
        o.z = a3_ * cx[ja] + a1_ * cy[ja] + c3_ * cx[jb] + c1_ * cy[jb] + b0;  \
        o.w = a2_ * cy[ja] + a0_ * R[ja]  + c2_ * cy[jb] + c0_ * R[jb]  + b0;  \
        __stcs(reinterpret_cast<float4*>(dst), o);                             \
    }

    OUT_ROW(ob + orow + 0 * OW, 0, w30, w31, w32, w33, 1, w10, w11, w12, w13);
    OUT_ROW(ob + orow + 1 * OW, 1, w20, w21, w22, w23, 2, w00, w01, w02, w03);
    OUT_ROW(ob + orow + 2 * OW, 1, w30, w31, w32, w33, 2, w10, w11, w12, w13);
    OUT_ROW(ob + orow + 3 * OW, 2, w20, w21, w22, w23, 3, w00, w01, w02, w03);
#undef OUT_ROW
}

extern "C" void kernel_launch(void* const* d_in, const int* in_sizes, int n_in,
                              void* d_out, int out_size) {
    const float* x = (const float*)d_in[0];
    const float* w = (const float*)d_in[1];
    const float* b = (const float*)d_in[2];
    float* out = (float*)d_out;

    const int B = in_sizes[0] / (NSLICE * H * W);   // = 8
    dim3 grid(OH / 4, B * NSLICE);                   // 128 x 192
    convT_kernel<<<grid, 128>>>(x, w, b, out);
}